// round 17
// baseline (speedup 1.0000x reference)
#include <cuda_runtime.h>
#include <math.h>
#include <stdint.h>

#define BB 16
#define NN 256
#define DD 128
#define KP 128
#define LOG2E 1.4426950408889634f

// -------- scratch (device globals; no allocation allowed) --------
__device__ float    d_logits[(size_t)BB * NN * NN];   // 4 MB (raw logits)
__device__ float    d_h[(size_t)BB * NN * DD];        // 2 MB
__device__ float    d_scores[BB * NN];
__device__ float    d_rowM[BB * NN];
__device__ float    d_rowIS[BB * NN];
__device__ uint32_t d_wbh[DD * 64];                   // W^T hi bf16x2 pairs [c][p]
__device__ uint32_t d_wbl[DD * 64];
__device__ uint32_t d_pah[DD * 64], d_pal[DD * 64];   // pwa_w^T pairs [c][p over d]
__device__ uint32_t d_poh[DD * 64], d_pol[DD * 64];   // pwoa_w^T pairs
__device__ uint32_t d_xrh[BB * NN * 64];              // x row-major pairs [b][j][p over d]
__device__ uint32_t d_xrl[BB * NN * 64];
__device__ uint32_t d_xth[BB * DD * 128];             // x^T pairs [b][d][p over j]
__device__ uint32_t d_xtl[BB * DD * 128];
__device__ float    d_bnsc[DD], d_bnof[DD];           // folded BN scale/offset

__device__ __forceinline__ float tanh_approx(float x) {
    float y; asm("tanh.approx.f32 %0, %1;" : "=f"(y) : "f"(x)); return y;
}
__device__ __forceinline__ uint32_t pack_bf16x2(float e0, float e1) {
    uint32_t u;
    asm("cvt.rn.bf16x2.f32 %0, %1, %2;" : "=r"(u) : "f"(e1), "f"(e0));
    return u;
}
__device__ __forceinline__ void split2(float a0, float a1, uint32_t& hi, uint32_t& lo) {
    hi = pack_bf16x2(a0, a1);
    float r0 = a0 - __uint_as_float(hi << 16);
    float r1 = a1 - __uint_as_float(hi & 0xffff0000u);
    lo = pack_bf16x2(r0, r1);
}
__device__ __forceinline__ void mma_bf16(float* c, const uint32_t* a,
                                         uint32_t b0, uint32_t b1) {
    asm volatile(
        "mma.sync.aligned.m16n8k16.row.col.f32.bf16.bf16.f32 "
        "{%0,%1,%2,%3}, {%4,%5,%6,%7}, {%8,%9}, {%0,%1,%2,%3};"
        : "+f"(c[0]), "+f"(c[1]), "+f"(c[2]), "+f"(c[3])
        : "r"(a[0]), "r"(a[1]), "r"(a[2]), "r"(a[3]), "r"(b0), "r"(b1));
}

// ============================================================================
// Kernel 0 (verified R16): preprocessing splits.
// ============================================================================
__global__ void k0_prep(const float* __restrict__ W, const float* __restrict__ x,
                        const float* __restrict__ pwa_w, const float* __restrict__ pwoa_w,
                        const float* __restrict__ pwa_b, const float* __restrict__ pwoa_b,
                        const float* __restrict__ bn_g, const float* __restrict__ bn_b,
                        const float* __restrict__ bn_m, const float* __restrict__ bn_v) {
    int blk = blockIdx.x, tid = threadIdx.x;
    if (blk < 32) {
        int idx = blk * 256 + tid;
        int c = idx >> 6, p = idx & 63;
        uint32_t hi, lo;
        split2(W[(size_t)(2 * p) * DD + c], W[(size_t)(2 * p + 1) * DD + c], hi, lo);
        d_wbh[idx] = hi; d_wbl[idx] = lo;
    } else if (blk < 96) {
        int idx = (blk - 32) * 256 + tid;
        int mat = idx >> 13;
        int r = idx & 8191;
        int c = r >> 6, p = r & 63;
        const float* src = mat ? pwoa_w : pwa_w;
        uint32_t hi, lo;
        split2(src[(size_t)(2 * p) * DD + c], src[(size_t)(2 * p + 1) * DD + c], hi, lo);
        if (mat) { d_poh[r] = hi; d_pol[r] = lo; }
        else     { d_pah[r] = hi; d_pal[r] = lo; }
    } else if (blk < 1120) {
        int idx = (blk - 96) * 256 + tid;   // b*16384 + j*64 + p
        int p = idx & 63;
        const float* xp = x + (size_t)(idx >> 6) * DD;
        uint32_t hi, lo;
        split2(xp[2 * p], xp[2 * p + 1], hi, lo);
        d_xrh[idx] = hi; d_xrl[idx] = lo;
    } else if (blk < 1184) {
        // coalesced smem transpose: batch bb, rows [rc*64, rc*64+64)
        __shared__ float ts[64 * 129];
        int q = blk - 1120;                 // 0..63
        int bb = q >> 2;                    // 0..15
        int rc = q & 3;                     // 0..3  (4 x 64 rows = 256)
        const float* xs = x + ((size_t)bb * NN + rc * 64) * DD;
        #pragma unroll
        for (int k = 0; k < 8; k++) {
            int e = k * 256 + tid;
            int r = e >> 5, c4 = e & 31;
            float4 v = ((const float4*)(xs + (size_t)r * DD))[c4];
            float* dstp = ts + r * 129 + c4 * 4;
            dstp[0] = v.x; dstp[1] = v.y; dstp[2] = v.z; dstp[3] = v.w;
        }
        __syncthreads();
        #pragma unroll
        for (int k = 0; k < 16; k++) {
            int e = k * 256 + tid;
            int d = e >> 5, pl = e & 31;
            float y0 = ts[(2 * pl) * 129 + d];
            float y1 = ts[(2 * pl + 1) * 129 + d];
            uint32_t hi, lo;
            split2(y0, y1, hi, lo);
            size_t o = ((size_t)bb * DD + d) * 128 + rc * 32 + pl;
            d_xth[o] = hi; d_xtl[o] = lo;
        }
    } else {
        if (tid < DD) {
            float sc = bn_g[tid] * rsqrtf(bn_v[tid] + 1e-5f);
            d_bnsc[tid] = sc;
            d_bnof[tid] = (pwa_b[tid] + pwoa_b[tid] - bn_m[tid]) * sc + bn_b[tid];
        }
    }
}

#define PPAD 68
// k1 smem (M=32): Ah/Al [32][PPAD], Bh/Bl [128][PPAD], XI[2][128], BSs, VS, PART[256]
#define SMEM1_REQ ((2 * 32 * PPAD + 2 * 128 * PPAD + 256 + 128 + 128 + 256) * 4)

// ============================================================================
// Kernel 1 (verified R13/R16): symmetric-pair, M=32 j-tiles, bf16x3 mma.
// ============================================================================
__global__ void __launch_bounds__(256, 2)
k1_mma(const float* __restrict__ x, const float* __restrict__ bias,
       const float* __restrict__ v) {
    extern __shared__ uint32_t sm[];
    uint32_t* Ah = sm;                        // [32][PPAD]
    uint32_t* Al = Ah + 32 * PPAD;
    uint32_t* Bh = Al + 32 * PPAD;            // [128][PPAD]
    uint32_t* Bl = Bh + 128 * PPAD;
    float* XI   = (float*)(Bl + 128 * PPAD);  // [2][128]
    float* BSs  = XI + 256;
    float* VS   = BSs + 128;
    float* PART = VS + 128;                   // [8][32]

    const int p = blockIdx.x, b = blockIdx.y;
    const int i1 = p, i2 = NN - 1 - p;
    const int tid = threadIdx.x;
    const int wid = tid >> 5, lid = tid & 31;
    const int g = lid >> 2, tig = lid & 3;
    const float* xb = x + (size_t)b * NN * DD;

    if (tid < 128) {
        XI[tid]       = xb[(size_t)i1 * DD + tid];
        XI[128 + tid] = xb[(size_t)i2 * DD + tid];
        BSs[tid] = bias[tid];
        VS[tid]  = v[tid];
    }
    #pragma unroll
    for (int k = 0; k < 8; k++) {
        int e = tid + k * 256;
        int r = e >> 4, c4 = e & 15;
        ((uint4*)(Bh + r * PPAD))[c4] = ((const uint4*)d_wbh)[e];
        ((uint4*)(Bl + r * PPAD))[c4] = ((const uint4*)d_wbl)[e];
    }
    __syncthreads();

    for (int xi = 0; xi < 2; xi++) {
        const int ii = xi ? i2 : i1;
        const float* xisel = XI + xi * 128;
        for (int j0 = 0; j0 < NN; j0 += 32) {
            if (j0 + 31 < ii) continue;
            const int jmin = (ii > j0) ? (ii - j0) : 0;

            {
                int r  = tid >> 3;
                int dg = (tid & 7) * 16;
                const float4* xr  = (const float4*)(xb + (size_t)(j0 + r) * DD + dg);
                const float4* xi4 = (const float4*)(xisel + dg);
                uint32_t* ahr = Ah + r * PPAD + (dg >> 1);
                uint32_t* alr = Al + r * PPAD + (dg >> 1);
                #pragma unroll
                for (int q = 0; q < 4; q++) {
                    float4 xv = xr[q], iv = xi4[q];
                    uint32_t h0, l0, h1, l1;
                    split2(xv.x * iv.x, xv.y * iv.y, h0, l0);
                    split2(xv.z * iv.z, xv.w * iv.w, h1, l1);
                    ahr[q * 2]     = h0;
                    ahr[q * 2 + 1] = h1;
                    alr[q * 2]     = l0;
                    alr[q * 2 + 1] = l1;
                }
            }
            __syncthreads();

            float acc[2][2][4];
            #pragma unroll
            for (int m = 0; m < 2; m++)
                #pragma unroll
                for (int n = 0; n < 2; n++)
                    #pragma unroll
                    for (int q = 0; q < 4; q++) acc[m][n][q] = 0.f;

            #pragma unroll
            for (int k = 0; k < 8; k++) {
                uint32_t ah[2][4], al[2][4];
                #pragma unroll
                for (int m = 0; m < 2; m++) {
                    const uint32_t* aph = Ah + (m * 16 + g) * PPAD + k * 8 + tig;
                    const uint32_t* apl = Al + (m * 16 + g) * PPAD + k * 8 + tig;
                    ah[m][0] = aph[0];            ah[m][1] = aph[8 * PPAD];
                    ah[m][2] = aph[4];            ah[m][3] = aph[8 * PPAD + 4];
                    al[m][0] = apl[0];            al[m][1] = apl[8 * PPAD];
                    al[m][2] = apl[4];            al[m][3] = apl[8 * PPAD + 4];
                }
                #pragma unroll
                for (int nf = 0; nf < 2; nf++) {
                    const uint32_t* bph = Bh + (wid * 16 + nf * 8 + g) * PPAD + k * 8 + tig;
                    const uint32_t* bpl = Bl + (wid * 16 + nf * 8 + g) * PPAD + k * 8 + tig;
                    uint32_t bh0 = bph[0], bh1 = bph[4];
                    uint32_t bl0 = bpl[0], bl1 = bpl[4];
                    mma_bf16(acc[0][nf], ah[0], bh0, bh1);
                    mma_bf16(acc[1][nf], ah[1], bh0, bh1);
                    mma_bf16(acc[0][nf], ah[0], bl0, bl1);
                    mma_bf16(acc[1][nf], ah[1], bl0, bl1);
                    mma_bf16(acc[0][nf], al[0], bh0, bh1);
                    mma_bf16(acc[1][nf], al[1], bh0, bh1);
                }
            }

            float prt[4] = {0.f, 0.f, 0.f, 0.f};
            #pragma unroll
            for (int m = 0; m < 2; m++) {
                #pragma unroll
                for (int nf = 0; nf < 2; nf++) {
                    int c0 = wid * 16 + nf * 8 + 2 * tig;
                    float v0 = VS[c0], v1 = VS[c0 + 1];
                    float b0 = BSs[c0], b1 = BSs[c0 + 1];
                    prt[2 * m + 0] += v0 * tanh_approx(acc[m][nf][0] + b0)
                                    + v1 * tanh_approx(acc[m][nf][1] + b1);
                    prt[2 * m + 1] += v0 * tanh_approx(acc[m][nf][2] + b0)
                                    + v1 * tanh_approx(acc[m][nf][3] + b1);
                }
            }
            #pragma unroll
            for (int o = 1; o <= 2; o <<= 1) {
                prt[0] += __shfl_xor_sync(0xffffffffu, prt[0], o);
                prt[1] += __shfl_xor_sync(0xffffffffu, prt[1], o);
                prt[2] += __shfl_xor_sync(0xffffffffu, prt[2], o);
                prt[3] += __shfl_xor_sync(0xffffffffu, prt[3], o);
            }
            if (tig == 0) {
                PART[wid * 32 + g]      = prt[0];
                PART[wid * 32 + g + 8]  = prt[1];
                PART[wid * 32 + g + 16] = prt[2];
                PART[wid * 32 + g + 24] = prt[3];
            }
            __syncthreads();
            if (tid < 32 && tid >= jmin) {
                float lg = 0.f;
                #pragma unroll
                for (int w = 0; w < 8; w++) lg += PART[w * 32 + tid];
                int j = j0 + tid;
                d_logits[((size_t)b * NN + ii) * NN + j] = lg;
                d_logits[((size_t)b * NN + j) * NN + ii] = lg;
            }
            __syncthreads();
        }
    }
}

// ============================================================================
// Kernel 2r: per-row max and 1/sum(exp).
// ============================================================================
__global__ void __launch_bounds__(256)
k2r_rowstat() {
    const int b = blockIdx.y;
    const int row = blockIdx.x * 8 + (threadIdx.x >> 5);
    const int lane = threadIdx.x & 31;
    const float* rp = d_logits + ((size_t)b * NN + row) * NN;

    float4 a0 = ((const float4*)rp)[lane * 2];
    float4 a1 = ((const float4*)rp)[lane * 2 + 1];
    float m = fmaxf(fmaxf(fmaxf(a0.x, a0.y), fmaxf(a0.z, a0.w)),
                    fmaxf(fmaxf(a1.x, a1.y), fmaxf(a1.z, a1.w)));
    #pragma unroll
    for (int o = 16; o > 0; o >>= 1) m = fmaxf(m, __shfl_xor_sync(0xffffffffu, m, o));

    float s = exp2f((a0.x - m) * LOG2E) + exp2f((a0.y - m) * LOG2E)
            + exp2f((a0.z - m) * LOG2E) + exp2f((a0.w - m) * LOG2E)
            + exp2f((a1.x - m) * LOG2E) + exp2f((a1.y - m) * LOG2E)
            + exp2f((a1.z - m) * LOG2E) + exp2f((a1.w - m) * LOG2E);
    #pragma unroll
    for (int o = 16; o > 0; o >>= 1) s += __shfl_xor_sync(0xffffffffu, s, o);

    if (lane == 0) {
        d_rowM[b * NN + row]  = m;
        d_rowIS[b * NN + row] = 1.f / s;
    }
}

// ============================================================================
// Kernel 3 (M=16 i-tiles, grid (16,16)): subset of verified M=32 fragment maps
// (m=0 path only). stage1: agg = att @ x; stage2: h = [agg|x] @ [pwaT;pwoaT];
// BN/selu/pool. 8 warps x 16 cols; 2 CTAs/SM.
// ============================================================================
#define SMEM3 ((2 * 16 * PPAD + 2 * 128 * PPAD) * 4 + (16 * 132 + 128) * 4)

__global__ void __launch_bounds__(256, 2)
k3_tc(const float* __restrict__ pool_w, const float* __restrict__ pool_b) {
    extern __shared__ uint32_t sm3u[];
    uint32_t* Ah = sm3u;                       // [16][PPAD]
    uint32_t* Al = Ah + 16 * PPAD;
    uint32_t* Bh = Al + 16 * PPAD;             // [128][PPAD]
    uint32_t* Bl = Bh + 128 * PPAD;
    float* Ag   = (float*)(Bl + 128 * PPAD);   // [16][132]; doubles as Et
    float* PART = Ag + 16 * 132;               // [8][16]

    const int b = blockIdx.y;
    const int it0 = blockIdx.x * 16;
    const int tid = threadIdx.x;
    const int wid = tid >> 5, lid = tid & 31;
    const int g = lid >> 2, tig = lid & 3;

    float acc[2][4];
    #pragma unroll
    for (int n = 0; n < 2; n++)
        #pragma unroll
        for (int q = 0; q < 4; q++) acc[n][q] = 0.f;

    // ---------------- stage 1: agg = att @ x ----------------
    for (int ch = 0; ch < 2; ch++) {
        const int j0 = ch * 128;
        // Et build: 128 j-rows x 4 float4 (16 cols), transposed into Ag
        #pragma unroll
        for (int k = 0; k < 2; k++) {
            int e = tid + k * 256;          // 0..511
            int jr = e >> 2, ic4 = e & 3;
            int row = j0 + jr;
            float M  = d_rowM[b * NN + row];
            float IS = d_rowIS[b * NN + row];
            float4 rv = ((const float4*)(d_logits + ((size_t)b * NN + row) * NN + it0))[ic4];
            Ag[(ic4 * 4 + 0) * 132 + jr] = exp2f((rv.x - M) * LOG2E) * IS;
            Ag[(ic4 * 4 + 1) * 132 + jr] = exp2f((rv.y - M) * LOG2E) * IS;
            Ag[(ic4 * 4 + 2) * 132 + jr] = exp2f((rv.z - M) * LOG2E) * IS;
            Ag[(ic4 * 4 + 3) * 132 + jr] = exp2f((rv.w - M) * LOG2E) * IS;
        }
        __syncthreads();
        // A split: 16 rows x 64 pairs = 1024
        #pragma unroll
        for (int k = 0; k < 4; k++) {
            int e = tid + k * 256;
            int i = e >> 6, pp = e & 63;
            float2 v2 = *(const float2*)(Ag + i * 132 + 2 * pp);
            uint32_t hi, lo;
            split2(v2.x, v2.y, hi, lo);
            Ah[i * PPAD + pp] = hi;
            Al[i * PPAD + pp] = lo;
        }
        // B copy: x^T pair slice
        #pragma unroll
        for (int k = 0; k < 8; k++) {
            int e = tid + k * 256;
            int r = e >> 4, c4 = e & 15;
            ((uint4*)(Bh + r * PPAD))[c4] =
                ((const uint4*)(d_xth + ((size_t)b * DD + r) * 128 + ch * 64))[c4];
            ((uint4*)(Bl + r * PPAD))[c4] =
                ((const uint4*)(d_xtl + ((size_t)b * DD + r) * 128 + ch * 64))[c4];
        }
        __syncthreads();
        #pragma unroll
        for (int k = 0; k < 8; k++) {
            uint32_t ah[4], al[4];
            const uint32_t* aph = Ah + g * PPAD + k * 8 + tig;
            const uint32_t* apl = Al + g * PPAD + k * 8 + tig;
            ah[0] = aph[0];            ah[1] = aph[8 * PPAD];
            ah[2] = aph[4];            ah[3] = aph[8 * PPAD + 4];
            al[0] = apl[0];            al[1] = apl[8 * PPAD];
            al[2] = apl[4];            al[3] = apl[8 * PPAD + 4];
            #pragma unroll
            for (int nf = 0; nf < 2; nf++) {
                const uint32_t* bph = Bh + (wid * 16 + nf * 8 + g) * PPAD + k * 8 + tig;
                const uint32_t* bpl = Bl + (wid * 16 + nf * 8 + g) * PPAD + k * 8 + tig;
                uint32_t bh0 = bph[0], bh1 = bph[4];
                uint32_t bl0 = bpl[0], bl1 = bpl[4];
                mma_bf16(acc[nf], ah, bh0, bh1);
                mma_bf16(acc[nf], ah, bl0, bl1);
                mma_bf16(acc[nf], al, bh0, bh1);
            }
        }
        __syncthreads();
    }
    // write agg (fp32) to Ag: rows g and g+8
    #pragma unroll
    for (int nf = 0; nf < 2; nf++) {
        int c0 = wid * 16 + nf * 8 + 2 * tig;
        Ag[g * 132 + c0]           = acc[nf][0];
        Ag[g * 132 + c0 + 1]       = acc[nf][1];
        Ag[(g + 8) * 132 + c0]     = acc[nf][2];
        Ag[(g + 8) * 132 + c0 + 1] = acc[nf][3];
    }
    __syncthreads();

    // ---------------- stage 2: h = [agg | x] @ [pwaT ; pwoaT] ----------------
    float hacc[2][4];
    #pragma unroll
    for (int n = 0; n < 2; n++)
        #pragma unroll
        for (int q = 0; q < 4; q++) hacc[n][q] = 0.f;

    for (int ch = 0; ch < 2; ch++) {
        if (ch == 0) {
            // A = agg split: 1024 pairs
            #pragma unroll
            for (int k = 0; k < 4; k++) {
                int e = tid + k * 256;
                int i = e >> 6, pp = e & 63;
                float2 v2 = *(const float2*)(Ag + i * 132 + 2 * pp);
                uint32_t hi, lo;
                split2(v2.x, v2.y, hi, lo);
                Ah[i * PPAD + pp] = hi;
                Al[i * PPAD + pp] = lo;
            }
        } else {
            // A = x rows it0..it0+15: 16 rows x 16 uint4 = 256
            {
                int e = tid;
                int r = e >> 4, c4 = e & 15;
                ((uint4*)(Ah + r * PPAD))[c4] =
                    ((const uint4*)(d_xrh + ((size_t)b * NN + it0 + r) * 64))[c4];
                ((uint4*)(Al + r * PPAD))[c4] =
                    ((const uint4*)(d_xrl + ((size_t)b * NN + it0 + r) * 64))[c4];
            }
        }
        const uint32_t* srcH = ch ? d_poh : d_pah;
        const uint32_t* srcL = ch ? d_pol : d_pal;
        #pragma unroll
        for (int k = 0; k < 8; k++) {
            int e = tid + k * 256;
            int r = e >> 4, c4 = e & 15;
            ((uint4*)(Bh + r * PPAD))[c4] = ((const uint4*)(srcH + r * 64))[c4];
            ((uint4*)(Bl + r * PPAD))[c4] = ((const uint4*)(srcL + r * 64))[c4];
        }
        __syncthreads();
        #pragma unroll
        for (int k = 0; k < 8; k++) {
            uint32_t ah[4], al[4];
            const uint32_t* aph = Ah + g * PPAD + k * 8 + tig;
            const uint32_t* apl = Al + g * PPAD + k * 8 + tig;
            ah[0] = aph[0];            ah[1] = aph[8 * PPAD];
            ah[2] = aph[4];            ah[3] = aph[8 * PPAD + 4];
            al[0] = apl[0];            al[1] = apl[8 * PPAD];
            al[2] = apl[4];            al[3] = apl[8 * PPAD + 4];
            #pragma unroll
            for (int nf = 0; nf < 2; nf++) {
                const uint32_t* bph = Bh + (wid * 16 + nf * 8 + g) * PPAD + k * 8 + tig;
                const uint32_t* bpl = Bl + (wid * 16 + nf * 8 + g) * PPAD + k * 8 + tig;
                uint32_t bh0 = bph[0], bh1 = bph[4];
                uint32_t bl0 = bpl[0], bl1 = bpl[4];
                mma_bf16(hacc[nf], ah, bh0, bh1);
                mma_bf16(hacc[nf], ah, bl0, bl1);
                mma_bf16(hacc[nf], al, bh0, bh1);
            }
        }
        __syncthreads();
    }

    // ---------------- epilogue: BN + selu + store + pool ----------------
    const float SELU_S = 1.0507009873554805f;
    const float SELU_A = 1.6732632423543772f;
    float prt[2] = {0.f, 0.f};
    #pragma unroll
    for (int nf = 0; nf < 2; nf++) {
        int c0 = wid * 16 + nf * 8 + 2 * tig;
        float sc0 = d_bnsc[c0], of0 = d_bnof[c0];
        float sc1 = d_bnsc[c0 + 1], of1 = d_bnof[c0 + 1];
        float pw0 = pool_w[c0], pw1 = pool_w[c0 + 1];
        #pragma unroll
        for (int half = 0; half < 2; half++) {
            int r = g + half * 8;
            float hv0 = hacc[nf][half * 2]     * sc0 + of0;
            float hv1 = hacc[nf][half * 2 + 1] * sc1 + of1;
            hv0 = (hv0 > 0.f) ? SELU_S * hv0 : SELU_S * SELU_A * (expf(hv0) - 1.f);
            hv1 = (hv1 > 0.f) ? SELU_S * hv1 : SELU_S * SELU_A * (expf(hv1) - 1.f);
            *(float2*)(d_h + ((size_t)b * NN + it0 + r) * DD + c0) =
                make_float2(hv0, hv1);
            prt[half] += hv0 * pw0 + hv1 * pw1;
        }
    }
    #pragma unroll
    for (int o = 1; o <= 2; o <<= 1) {
        prt[0] += __shfl_xor_sync(0xffffffffu, prt[0], o);
        prt[1] += __shfl_xor_sync(0xffffffffu, prt[1], o);
    }
    if (tig == 0) {
        PART[wid * 16 + g]     = prt[0];
        PART[wid * 16 + g + 8] = prt[1];
    }
    __syncthreads();
    if (tid < 16) {
        float pacc = 0.f;
        #pragma unroll
        for (int w = 0; w < 8; w++) pacc += PART[w * 16 + tid];
        float sg = 1.f / (1.f + expf(-(pacc + pool_b[0])));
        d_scores[b * NN + it0 + tid] = sg;
    }
}

// ============================================================================
// Kernel 4: fused rank-select + gather.
// ============================================================================
__global__ void __launch_bounds__(256)
k4_topk(float* __restrict__ out) {
    const int b = blockIdx.y;
    const int q = blockIdx.x;
    const int tid = threadIdx.x;
    __shared__ float ss[NN];
    __shared__ int sp[KP];

    float s = d_scores[b * NN + tid];
    ss[tid] = s;
    __syncthreads();

    int r = 0;
    #pragma unroll 16
    for (int j = 0; j < NN; j++) {
        float sj = ss[j];
        r += (sj > s) || (sj == s && j < tid);
    }
    if (r < KP) sp[r] = tid;
    __syncthreads();

    #pragma unroll
    for (int k = 0; k < 4; k++) {
        int e = q * 1024 + k * 256 + tid;
        int row = e >> 5, c4 = e & 31;
        int j = sp[row];
        float sv = ss[j];
        float4 v = ((const float4*)(d_h + ((size_t)b * NN + j) * DD))[c4];
        ((float4*)(out + ((size_t)b * KP + row) * DD))[c4] =
            make_float4(v.x * sv, v.y * sv, v.z * sv, v.w * sv);
    }
}

// ============================================================================
extern "C" void kernel_launch(void* const* d_in, const int* in_sizes, int n_in,
                              void* d_out, int out_size) {
    const float* x        = (const float*)d_in[0];
    const float* apw      = (const float*)d_in[1];
    const float* apb      = (const float*)d_in[2];
    const float* aweight  = (const float*)d_in[3];
    const float* pwa_w    = (const float*)d_in[4];
    const float* pwa_b    = (const float*)d_in[5];
    const float* pwoa_w   = (const float*)d_in[6];
    const float* pwoa_b   = (const float*)d_in[7];
    const float* bn_g     = (const float*)d_in[8];
    const float* bn_b     = (const float*)d_in[9];
    const float* bn_m     = (const float*)d_in[10];
    const float* bn_v     = (const float*)d_in[11];
    const float* pool_w   = (const float*)d_in[12];
    const float* pool_b   = (const float*)d_in[13];
    float* out = (float*)d_out;

    cudaFuncSetAttribute(k1_mma, cudaFuncAttributeMaxDynamicSharedMemorySize, SMEM1_REQ);
    cudaFuncSetAttribute(k3_tc,  cudaFuncAttributeMaxDynamicSharedMemorySize, SMEM3);

    k0_prep<<<1185, 256>>>(apw, x, pwa_w, pwoa_w, pwa_b, pwoa_b,
                           bn_g, bn_b, bn_m, bn_v);
    k1_mma<<<dim3(NN / 2, BB), 256, SMEM1_REQ>>>(x, apb, aweight);
    k2r_rowstat<<<dim3(NN / 8, BB), 256>>>();
    k3_tc<<<dim3(NN / 16, BB), 256, SMEM3>>>(pool_w, pool_b);
    k4_topk<<<dim3(4, BB), 256>>>(out);
}